// round 4
// baseline (speedup 1.0000x reference)
#include <cuda_runtime.h>
#include <cuda_bf16.h>
#include <cstdint>

// Problem constants
#define BATCH 4
#define TLEN  4096
#define DIM   1024
#define NH    16
#define HD    64
#define K3    3072           // split-bf16 K' = 3*DIM

// ---------------------------------------------------------------------------
// Scratch (device globals; no allocation allowed)
// ---------------------------------------------------------------------------
__device__ static __align__(256) float g_kv[BATCH * TLEN * 2 * DIM];   // 128 MB
__device__ static __align__(256) float g_Z [BATCH * DIM];
__device__ static __align__(256) unsigned g_kmaxKey[BATCH * DIM];
__device__ static __align__(256) float g_Cp[BATCH * NH * 8 * HD * HD];
__device__ static __align__(256) float g_Cn[BATCH * NH * HD * HD];
__device__ static __align__(256) float g_E [BATCH * DIM * DIM];        // 16 MB

__device__ static __align__(256) __nv_bfloat16 g_zs [(long)BATCH * TLEN * K3]; // 100.7 MB
__device__ static __align__(256) __nv_bfloat16 g_xs [(long)BATCH * TLEN * K3];
__device__ static __align__(256) __nv_bfloat16 g_qs [(long)BATCH * TLEN * K3];
__device__ static __align__(256) __nv_bfloat16 g_wkvs[(long)2 * DIM * K3];
__device__ static __align__(256) __nv_bfloat16 g_wqs [(long)DIM * K3];
__device__ static __align__(256) __nv_bfloat16 g_Es  [(long)BATCH * DIM * K3];

// ---------------------------------------------------------------------------
// Helpers
// ---------------------------------------------------------------------------
#define SW128(o) ((o) ^ (((o) >> 3) & 0x70))

static __device__ __forceinline__ uint32_t su32(const void* p) {
    uint32_t a;
    asm("{ .reg .u64 t; cvta.to.shared.u64 t, %1; cvt.u32.u64 %0, t; }" : "=r"(a) : "l"(p));
    return a;
}

// monotone float <-> unsigned key (for atomicMax over floats)
static __device__ __forceinline__ unsigned fkey(float f) {
    unsigned i = __float_as_uint(f);
    return (i & 0x80000000u) ? ~i : (i | 0x80000000u);
}
static __device__ __forceinline__ float fdec(unsigned k) {
    unsigned i = (k & 0x80000000u) ? (k & 0x7FFFFFFFu) : ~k;
    return __uint_as_float(i);
}

#define CP16(dst, src)   asm volatile("cp.async.cg.shared.global [%0], [%1], 16;" :: "r"(dst), "l"(src))
#define CP_COMMIT()      asm volatile("cp.async.commit_group;" ::: "memory")
#define CP_WAIT(n)       asm volatile("cp.async.wait_group %0;" :: "n"(n) : "memory")

#define LDSM4(r0, r1, r2, r3, addr) \
    asm volatile("ldmatrix.sync.aligned.m8n8.x4.shared.b16 {%0,%1,%2,%3}, [%4];" \
        : "=r"(r0), "=r"(r1), "=r"(r2), "=r"(r3) : "r"(addr))

#define MMA16816(d, a, b) \
    asm volatile("mma.sync.aligned.m16n8k16.row.col.f32.bf16.bf16.f32 " \
        "{%0,%1,%2,%3},{%4,%5,%6,%7},{%8,%9},{%0,%1,%2,%3};" \
        : "+f"((d)[0]), "+f"((d)[1]), "+f"((d)[2]), "+f"((d)[3]) \
        : "r"((a)[0]), "r"((a)[1]), "r"((a)[2]), "r"((a)[3]), "r"((b)[0]), "r"((b)[1]))

// ---------------------------------------------------------------------------
// mma.sync bf16 GEMM:  C[M,N] = A'[M,K3] * B'[N,K3]^T + bias
// BM=128, BN=256, BK=64 (128B rows, SW128), 4-stage cp.async, 8 warps (2x4),
// warp tile 64x64. split=1: write split-bf16 [hi|lo|hi] rows of width K3.
// kmaxN>0: per-(batch,col) atomicMax of output (cols < kmaxN) into kmaxKey.
// grid = (N/256, M/128, batch)
// ---------------------------------------------------------------------------
#define GNK      (K3 / 64)          // 48 k-tiles
#define NSTG     4
#define A_TILE_B 16384              // 128 rows x 128 B
#define B_TILE_B 32768              // 256 rows x 128 B
#define STG_B    (A_TILE_B + B_TILE_B)
#define GSMEM    (NSTG * STG_B)     // 192 KB

extern __shared__ __align__(1024) char gsm_raw[];

__global__ __launch_bounds__(256, 1)
void gemm_mma(const __nv_bfloat16* __restrict__ A, const __nv_bfloat16* __restrict__ B,
              const float* __restrict__ bias, float* __restrict__ Cf,
              __nv_bfloat16* __restrict__ Cs, int N, int split,
              unsigned* __restrict__ kmaxKey, int kmaxN,
              long sA, long sB, long sC)
{
    A += blockIdx.z * sA; B += blockIdx.z * sB;
    const int m0 = blockIdx.y * 128;
    const int n0 = blockIdx.x * 256;
    const uint32_t sbase = su32(gsm_raw);
    const int tid = threadIdx.x, wid = tid >> 5, lane = tid & 31;

    const __nv_bfloat16* Arow = A + (long)m0 * K3;
    const __nv_bfloat16* Brow = B + (long)n0 * K3;

    auto load_tile = [&](int kt, int s) {
        const uint32_t sa = sbase + s * STG_B;
        const uint32_t sb = sa + A_TILE_B;
        const __nv_bfloat16* Ab = Arow + kt * 64;
        const __nv_bfloat16* Bb = Brow + kt * 64;
#pragma unroll
        for (int it = 0; it < 12; it++) {
            int i = tid + it * 256;
            if (it < 4) {                        // A: i in [0,1024)
                int row = i >> 3, ch = (i & 7) * 16;
                CP16(sa + SW128(row * 128 + ch), Ab + (long)row * K3 + ch / 2);
            } else {                             // B: j in [0,2048)
                int j = i - 1024;
                int row = j >> 3, ch = (j & 7) * 16;
                CP16(sb + SW128(row * 128 + ch), Bb + (long)row * K3 + ch / 2);
            }
        }
    };

    float acc[4][8][4];
#pragma unroll
    for (int mf = 0; mf < 4; mf++)
#pragma unroll
        for (int nf = 0; nf < 8; nf++)
#pragma unroll
            for (int r = 0; r < 4; r++) acc[mf][nf][r] = 0.f;

    const int wm = wid >> 2, wn = wid & 3;
    const int a_row = wm * 64 + (lane & 15);                      // + mf*16
    const int a_sec = (lane >> 4) * 16;
    const int b_row = wn * 64 + (lane & 7) + ((lane >> 4) << 3);  // + nf2*16
    const int b_sec = ((lane >> 3) & 1) * 16;

    load_tile(0, 0); CP_COMMIT();
    load_tile(1, 1); CP_COMMIT();
    load_tile(2, 2); CP_COMMIT();

    for (int kt = 0; kt < GNK; kt++) {
        const int kn = kt + 3;
        if (kn < GNK) { load_tile(kn, kn & 3); CP_COMMIT(); CP_WAIT(3); }
        else if (kt == GNK - 3) CP_WAIT(2);
        else if (kt == GNK - 2) CP_WAIT(1);
        else CP_WAIT(0);
        __syncthreads();

        const uint32_t sa = sbase + (kt & 3) * STG_B;
        const uint32_t sb = sa + A_TILE_B;
#pragma unroll
        for (int ks = 0; ks < 4; ks++) {
            uint32_t af[4][4], bf[8][2];
#pragma unroll
            for (int mf = 0; mf < 4; mf++)
                LDSM4(af[mf][0], af[mf][1], af[mf][2], af[mf][3],
                      sa + SW128((a_row + mf * 16) * 128 + ks * 32 + a_sec));
#pragma unroll
            for (int nf2 = 0; nf2 < 4; nf2++)
                LDSM4(bf[nf2 * 2][0], bf[nf2 * 2][1], bf[nf2 * 2 + 1][0], bf[nf2 * 2 + 1][1],
                      sb + SW128((b_row + nf2 * 16) * 128 + ks * 32 + b_sec));
#pragma unroll
            for (int nf = 0; nf < 8; nf++)
#pragma unroll
                for (int mf = 0; mf < 4; mf++)
                    MMA16816(acc[mf][nf], af[mf], bf[nf]);
        }
        __syncthreads();
    }

    // Epilogue
#pragma unroll
    for (int nf = 0; nf < 8; nf++) {
        const int col = n0 + wn * 64 + nf * 8 + (lane & 3) * 2;
        const float b0 = __ldg(bias + col), b1 = __ldg(bias + col + 1);
        float cm0 = -3.402823466e38f, cm1 = -3.402823466e38f;
#pragma unroll
        for (int mf = 0; mf < 4; mf++) {
            const int row = m0 + wm * 64 + mf * 16 + (lane >> 2);
            float v0 = acc[mf][nf][0] + b0, v1 = acc[mf][nf][1] + b1;
            float v2 = acc[mf][nf][2] + b0, v3 = acc[mf][nf][3] + b1;
            if (!split) {
                float* c0 = Cf + blockIdx.z * sC + (long)row * N + col;
                float2 p0; p0.x = v0; p0.y = v1; *(float2*)c0 = p0;
                float2 p1; p1.x = v2; p1.y = v3; *(float2*)(c0 + 8 * N) = p1;
            } else {
                __nv_bfloat16 h0 = __float2bfloat16(v0), h1 = __float2bfloat16(v1);
                __nv_bfloat16 h2 = __float2bfloat16(v2), h3 = __float2bfloat16(v3);
                __nv_bfloat16 l0 = __float2bfloat16(v0 - __bfloat162float(h0));
                __nv_bfloat16 l1 = __float2bfloat16(v1 - __bfloat162float(h1));
                __nv_bfloat16 l2 = __float2bfloat16(v2 - __bfloat162float(h2));
                __nv_bfloat16 l3 = __float2bfloat16(v3 - __bfloat162float(h3));
                __nv_bfloat16* o0 = Cs + (long)row * K3 + col;
                __nv_bfloat16* o1 = Cs + (long)(row + 8) * K3 + col;
                __nv_bfloat162 p;
                p.x = h0; p.y = h1; *(__nv_bfloat162*)o0 = p; *(__nv_bfloat162*)(o0 + 2 * DIM) = p;
                p.x = l0; p.y = l1; *(__nv_bfloat162*)(o0 + DIM) = p;
                p.x = h2; p.y = h3; *(__nv_bfloat162*)o1 = p; *(__nv_bfloat162*)(o1 + 2 * DIM) = p;
                p.x = l2; p.y = l3; *(__nv_bfloat162*)(o1 + DIM) = p;
            }
            cm0 = fmaxf(cm0, fmaxf(v0, v2));
            cm1 = fmaxf(cm1, fmaxf(v1, v3));
        }
        if (col < kmaxN) {       // uniform across warp (kmaxN multiple of 64)
#pragma unroll
            for (int sh = 4; sh < 32; sh <<= 1) {
                cm0 = fmaxf(cm0, __shfl_xor_sync(0xffffffffu, cm0, sh));
                cm1 = fmaxf(cm1, __shfl_xor_sync(0xffffffffu, cm1, sh));
            }
            if ((lane >> 2) == 0) {
                const int b_idx = m0 >> 12;     // rows within one batch (128 | 4096)
                atomicMax(kmaxKey + b_idx * DIM + col, fkey(cm0));
                atomicMax(kmaxKey + b_idx * DIM + col + 1, fkey(cm1));
            }
        }
    }
}

// ---------------------------------------------------------------------------
// init: zero softmax accumulators (persisted device globals)
// ---------------------------------------------------------------------------
__global__ __launch_bounds__(256)
void init_stats()
{
    int i = blockIdx.x * 256 + threadIdx.x;
    if (i < BATCH * DIM) { g_kmaxKey[i] = 0u; g_Z[i] = 0.f; }
}

// ---------------------------------------------------------------------------
// split-bf16 conversions
// ---------------------------------------------------------------------------
__global__ __launch_bounds__(256)
void split_act(const float* __restrict__ in, __nv_bfloat16* __restrict__ out, long total4)
{
    for (long idx = blockIdx.x * 256L + threadIdx.x; idx < total4; idx += gridDim.x * 256L) {
        float4 v = ((const float4*)in)[idx];
        long m = idx >> 8;
        int c = (int)(idx & 255) * 4;
        __nv_bfloat16 h0 = __float2bfloat16(v.x), h1 = __float2bfloat16(v.y);
        __nv_bfloat16 h2 = __float2bfloat16(v.z), h3 = __float2bfloat16(v.w);
        __nv_bfloat16 l0 = __float2bfloat16(v.x - __bfloat162float(h0));
        __nv_bfloat16 l1 = __float2bfloat16(v.y - __bfloat162float(h1));
        __nv_bfloat16 l2 = __float2bfloat16(v.z - __bfloat162float(h2));
        __nv_bfloat16 l3 = __float2bfloat16(v.w - __bfloat162float(h3));
        __nv_bfloat16* o = out + m * K3 + c;
        __nv_bfloat162 p;
        p.x = h0; p.y = h1; ((__nv_bfloat162*)o)[0] = p;
        p.x = h2; p.y = h3; ((__nv_bfloat162*)o)[1] = p;
        p.x = h0; p.y = h1; ((__nv_bfloat162*)(o + 2 * DIM))[0] = p;
        p.x = h2; p.y = h3; ((__nv_bfloat162*)(o + 2 * DIM))[1] = p;
        p.x = l0; p.y = l1; ((__nv_bfloat162*)(o + DIM))[0] = p;
        p.x = l2; p.y = l3; ((__nv_bfloat162*)(o + DIM))[1] = p;
    }
}

__global__ __launch_bounds__(256)
void split_wt(const float* __restrict__ in, __nv_bfloat16* __restrict__ out,
              int N, long sin, long sout)
{
    __shared__ float t[32][33];
    in += blockIdx.z * sin; out += blockIdx.z * sout;
    const int n0 = blockIdx.x * 32, k0 = blockIdx.y * 32;
    const int tx = threadIdx.x & 31, ty = threadIdx.x >> 5;
#pragma unroll
    for (int i = 0; i < 4; i++)
        t[ty + i * 8][tx] = in[(long)(k0 + ty + i * 8) * N + n0 + tx];
    __syncthreads();
#pragma unroll
    for (int i = 0; i < 4; i++) {
        const int nn = ty + i * 8;
        float v = t[tx][nn];
        __nv_bfloat16 hi = __float2bfloat16(v);
        __nv_bfloat16 lo = __float2bfloat16(v - __bfloat162float(hi));
        __nv_bfloat16* o = out + (long)(n0 + nn) * K3 + k0 + tx;
        o[0] = hi; o[DIM] = hi; o[2 * DIM] = lo;
    }
}

// ---------------------------------------------------------------------------
// Context partial with fused exp + Z accumulation.
// grid (64, 8): each block handles one (b,h) over a 512-timestep slice.
// ---------------------------------------------------------------------------
__global__ __launch_bounds__(256)
void context_part()
{
    const int bh = blockIdx.x;
    const int tc = blockIdx.y;
    const int b = bh >> 4;
    const int h = bh & 15;

    const float* kbase = g_kv + (long)b * TLEN * (2 * DIM) + h * HD;
    const float* vbase = kbase + DIM;

    __shared__ float ks[32][68];
    __shared__ float vs[32][68];
    __shared__ float kmaxs[64];
    __shared__ float sZ[64];

    const int tid = threadIdx.x;
    const int tx = tid & 15;
    const int ty = tid >> 4;

    if (tid < 64) {
        kmaxs[tid] = fdec(g_kmaxKey[b * DIM + h * HD + tid]);
        sZ[tid] = 0.f;
    }
    __syncthreads();

    const int c4 = (tid & 15) * 4;
    float4 km;
    km.x = kmaxs[c4]; km.y = kmaxs[c4 + 1]; km.z = kmaxs[c4 + 2]; km.w = kmaxs[c4 + 3];
    float z0 = 0.f, z1 = 0.f, z2 = 0.f, z3 = 0.f;

    float acc[4][4];
#pragma unroll
    for (int i = 0; i < 4; i++)
#pragma unroll
        for (int j = 0; j < 4; j++) acc[i][j] = 0.f;

    for (int t0 = tc * 512; t0 < tc * 512 + 512; t0 += 32) {
#pragma unroll
        for (int ii = 0; ii < 2; ii++) {
            const int i = tid + ii * 256;
            const int r = i >> 4;
            float4 kv4 = *(const float4*)(kbase + (long)(t0 + r) * (2 * DIM) + c4);
            float4 e;
            e.x = expf(kv4.x - km.x); e.y = expf(kv4.y - km.y);
            e.z = expf(kv4.z - km.z); e.w = expf(kv4.w - km.w);
            *(float4*)&ks[r][c4] = e;
            z0 += e.x; z1 += e.y; z2 += e.z; z3 += e.w;
            *(float4*)&vs[r][c4] = *(const float4*)(vbase + (long)(t0 + r) * (2 * DIM) + c4);
        }
        __syncthreads();
#pragma unroll 8
        for (int kk = 0; kk < 32; kk++) {
            float rd[4], rv[4];
#pragma unroll
            for (int i = 0; i < 4; i++) rd[i] = ks[kk][ty * 4 + i];
#pragma unroll
            for (int j = 0; j < 4; j++) rv[j] = vs[kk][tx * 4 + j];
#pragma unroll
            for (int i = 0; i < 4; i++)
#pragma unroll
                for (int j = 0; j < 4; j++)
                    acc[i][j] = fmaf(rd[i], rv[j], acc[i][j]);
        }
        __syncthreads();
    }

    atomicAdd(&sZ[c4], z0);
    atomicAdd(&sZ[c4 + 1], z1);
    atomicAdd(&sZ[c4 + 2], z2);
    atomicAdd(&sZ[c4 + 3], z3);

    float* out = g_Cp + ((long)bh * 8 + tc) * (HD * HD);
#pragma unroll
    for (int i = 0; i < 4; i++)
#pragma unroll
        for (int j = 0; j < 4; j++)
            out[(ty * 4 + i) * HD + tx * 4 + j] = acc[i][j];

    __syncthreads();
    if (tid < 64)
        atomicAdd(&g_Z[b * DIM + h * HD + tid], sZ[tid]);
}

__global__ __launch_bounds__(256)
void context_reduce()
{
    const int bh = blockIdx.x;
    const int b = bh >> 4, h = bh & 15;
    for (int i = threadIdx.x; i < HD * HD; i += 256) {
        float s = 0.f;
#pragma unroll
        for (int c = 0; c < 8; c++)
            s += g_Cp[((long)bh * 8 + c) * (HD * HD) + i];
        const int d = i >> 6;
        g_Cn[(long)bh * (HD * HD) + i] = s / g_Z[b * DIM + h * HD + d];
    }
}

// ---------------------------------------------------------------------------
// Expand: E_b[h*64+d][n] = sum_w Cn[b,h][d][w] * W_out[h*64+w][n]
// ---------------------------------------------------------------------------
__global__ __launch_bounds__(256)
void expand_kernel(const float* __restrict__ w_out)
{
    const int bh = blockIdx.y;
    const int b = bh >> 4;
    const int h = bh & 15;
    const int cb = blockIdx.x * 128;

    __shared__ float cs[64][64];
    __shared__ float ws[64][128];

    const int tid = threadIdx.x;
    for (int i = tid; i < 1024; i += 256) {
        const int r = i >> 4;
        const int c = (i & 15) * 4;
        *(float4*)&cs[r][c] = *(const float4*)(g_Cn + (long)bh * 4096 + r * 64 + c);
    }
    for (int i = tid; i < 2048; i += 256) {
        const int r = i >> 5;
        const int c = (i & 31) * 4;
        *(float4*)&ws[r][c] = *(const float4*)(w_out + (long)(h * HD + r) * DIM + cb + c);
    }
    __syncthreads();

    const int tx = tid & 31;
    const int ty = tid >> 5;

    float acc[8][4];
#pragma unroll
    for (int rr = 0; rr < 8; rr++)
#pragma unroll
        for (int j = 0; j < 4; j++) acc[rr][j] = 0.f;

#pragma unroll 4
    for (int w = 0; w < 64; w++) {
        float4 wv = *(float4*)&ws[w][tx * 4];
#pragma unroll
        for (int rr = 0; rr < 8; rr++) {
            const float cv = cs[ty + rr * 8][w];
            acc[rr][0] = fmaf(cv, wv.x, acc[rr][0]);
            acc[rr][1] = fmaf(cv, wv.y, acc[rr][1]);
            acc[rr][2] = fmaf(cv, wv.z, acc[rr][2]);
            acc[rr][3] = fmaf(cv, wv.w, acc[rr][3]);
        }
    }

#pragma unroll
    for (int rr = 0; rr < 8; rr++) {
        const int row = ty + rr * 8;
        float4 o; o.x = acc[rr][0]; o.y = acc[rr][1]; o.z = acc[rr][2]; o.w = acc[rr][3];
        *(float4*)(g_E + ((long)b * DIM + h * HD + row) * DIM + cb + tx * 4) = o;
    }
}

// ---------------------------------------------------------------------------
extern "C" void kernel_launch(void* const* d_in, const int* in_sizes, int n_in,
                              void* d_out, int out_size)
{
    const float* x     = (const float*)d_in[0];
    const float* z     = (const float*)d_in[1];
    const float* w_q   = (const float*)d_in[2];
    const float* b_q   = (const float*)d_in[3];
    const float* w_kv  = (const float*)d_in[4];
    const float* b_kv  = (const float*)d_in[5];
    const float* w_out = (const float*)d_in[6];
    const float* b_out = (const float*)d_in[7];
    float* out = (float*)d_out;

    float *kv, *E;
    unsigned* kmaxKey;
    __nv_bfloat16 *zs, *xs, *qs, *wkvs, *wqs, *Es;
    cudaGetSymbolAddress((void**)&kv, g_kv);
    cudaGetSymbolAddress((void**)&E, g_E);
    cudaGetSymbolAddress((void**)&kmaxKey, g_kmaxKey);
    cudaGetSymbolAddress((void**)&zs, g_zs);
    cudaGetSymbolAddress((void**)&xs, g_xs);
    cudaGetSymbolAddress((void**)&qs, g_qs);
    cudaGetSymbolAddress((void**)&wkvs, g_wkvs);
    cudaGetSymbolAddress((void**)&wqs, g_wqs);
    cudaGetSymbolAddress((void**)&Es, g_Es);

    cudaFuncSetAttribute(gemm_mma, cudaFuncAttributeMaxDynamicSharedMemorySize, GSMEM);

    const int M = BATCH * TLEN;          // 16384
    const long tot4 = (long)M * DIM / 4;

    // 0. zero softmax accumulators (device globals persist across replays)
    init_stats<<<16, 256>>>();
    // 1. weight splits
    { dim3 g(2 * DIM / 32, DIM / 32, 1); split_wt<<<g, 256>>>(w_kv, wkvs, 2 * DIM, 0, 0); }
    { dim3 g(DIM / 32, DIM / 32, 1);     split_wt<<<g, 256>>>(w_q, wqs, DIM, 0, 0); }
    // 2. activation splits
    split_act<<<2048, 256>>>(z, zs, tot4);
    split_act<<<2048, 256>>>(x, xs, tot4);
    // 3. kv = z @ w_kv + b_kv  (fp32 out; fused per-(b,col) max of k half)
    { dim3 g(2 * DIM / 256, M / 128, 1);
      gemm_mma<<<g, 256, GSMEM>>>(zs, wkvs, b_kv, kv, nullptr, 2 * DIM, 0,
                                  kmaxKey, DIM, 0, 0, 0); }
    // 4. q = x @ w_q + b_q  (split-bf16 out straight into g_qs)
    { dim3 g(DIM / 256, M / 128, 1);
      gemm_mma<<<g, 256, GSMEM>>>(xs, wqs, b_q, nullptr, qs, DIM, 1,
                                  kmaxKey, 0, 0, 0, 0); }
    // 5. context (fused exp + Z; partials over T, then reduce+normalize)
    { dim3 g(BATCH * NH, 8); context_part<<<g, 256>>>(); }
    context_reduce<<<BATCH * NH, 256>>>();
    // 6. E_b = blockdiag(Cn) @ W_out
    { dim3 g(DIM / 128, BATCH * NH); expand_kernel<<<g, 256>>>(w_out); }
    // 7. split E (batched transpose+split)
    { dim3 g(DIM / 32, DIM / 32, BATCH); split_wt<<<g, 256>>>(E, Es, DIM, (long)DIM * DIM, (long)DIM * K3); }
    // 8. out_b = q_b @ E_b + b_out (batched, fp32 out)
    { dim3 g(DIM / 256, TLEN / 128, BATCH);
      gemm_mma<<<g, 256, GSMEM>>>(qs, Es, b_out, out, nullptr, DIM, 0,
                                  kmaxKey, 0, (long)TLEN * K3, (long)DIM * K3, (long)TLEN * DIM); }
}

// round 5
// speedup vs baseline: 1.3430x; 1.3430x over previous
#include <cuda_runtime.h>
#include <cuda_fp16.h>
#include <cstdint>

// Problem constants
#define BATCH 4
#define TLEN  4096
#define DIM   1024
#define NH    16
#define HD    64
#define K2    2048           // split-fp16 K' = 2*DIM

// ---------------------------------------------------------------------------
// Scratch (device globals; no allocation allowed)
// ---------------------------------------------------------------------------
__device__ static __align__(256) float g_kv[BATCH * TLEN * 2 * DIM];   // 128 MB
__device__ static __align__(256) float g_Z [BATCH * DIM];
__device__ static __align__(256) unsigned g_kmaxKey[BATCH * DIM];
__device__ static __align__(256) float g_Cp[BATCH * NH * 8 * HD * HD];
__device__ static __align__(256) float g_Cn[BATCH * NH * HD * HD];
__device__ static __align__(256) float g_E [BATCH * DIM * DIM];        // 16 MB

__device__ static __align__(256) __half g_zs [(long)BATCH * TLEN * K2]; // 67 MB
__device__ static __align__(256) __half g_xs [(long)BATCH * TLEN * K2];
__device__ static __align__(256) __half g_qs [(long)BATCH * TLEN * K2];
__device__ static __align__(256) __half g_wkvs[(long)2 * DIM * K2];
__device__ static __align__(256) __half g_wqs [(long)DIM * K2];
__device__ static __align__(256) __half g_Es  [(long)BATCH * DIM * K2];

// ---------------------------------------------------------------------------
// Helpers
// ---------------------------------------------------------------------------
#define SW128(o) ((o) ^ (((o) >> 3) & 0x70))

static __device__ __forceinline__ uint32_t su32(const void* p) {
    uint32_t a;
    asm("{ .reg .u64 t; cvta.to.shared.u64 t, %1; cvt.u32.u64 %0, t; }" : "=r"(a) : "l"(p));
    return a;
}

// monotone float <-> unsigned key (for atomicMax over floats)
static __device__ __forceinline__ unsigned fkey(float f) {
    unsigned i = __float_as_uint(f);
    return (i & 0x80000000u) ? ~i : (i | 0x80000000u);
}
static __device__ __forceinline__ float fdec(unsigned k) {
    unsigned i = (k & 0x80000000u) ? (k & 0x7FFFFFFFu) : ~k;
    return __uint_as_float(i);
}

#define CP16(dst, src)   asm volatile("cp.async.cg.shared.global [%0], [%1], 16;" :: "r"(dst), "l"(src))
#define CP_COMMIT()      asm volatile("cp.async.commit_group;" ::: "memory")
#define CP_WAIT(n)       asm volatile("cp.async.wait_group %0;" :: "n"(n) : "memory")

#define LDSM4(r0, r1, r2, r3, addr) \
    asm volatile("ldmatrix.sync.aligned.m8n8.x4.shared.b16 {%0,%1,%2,%3}, [%4];" \
        : "=r"(r0), "=r"(r1), "=r"(r2), "=r"(r3) : "r"(addr))

#define MMA16816(d, a, b) \
    asm volatile("mma.sync.aligned.m16n8k16.row.col.f32.f16.f16.f32 " \
        "{%0,%1,%2,%3},{%4,%5,%6,%7},{%8,%9},{%0,%1,%2,%3};" \
        : "+f"((d)[0]), "+f"((d)[1]), "+f"((d)[2]), "+f"((d)[3]) \
        : "r"((a)[0]), "r"((a)[1]), "r"((a)[2]), "r"((a)[3]), "r"((b)[0]), "r"((b)[1]))

// ---------------------------------------------------------------------------
// mma.sync fp16 GEMM:  C[M,N] = A'[M,K2] * B'[N,K2]^T + bias
// BM=128, BN=256, BK=64 (128B rows, SW128), 2-stage cp.async (96KB -> 2 CTA/SM),
// 8 warps (2x4), warp tile 64x64. split=1: write split-fp16 [hi|lo], width K2.
// kmaxN>0: per-(batch,col) atomicMax of output (cols < kmaxN) into kmaxKey.
// grid = (N/256, M/128, batch)
// ---------------------------------------------------------------------------
#define GNK      (K2 / 64)          // 32 k-tiles
#define NSTG     2
#define A_TILE_B 16384              // 128 rows x 128 B
#define B_TILE_B 32768              // 256 rows x 128 B
#define STG_B    (A_TILE_B + B_TILE_B)
#define GSMEM    (NSTG * STG_B)     // 96 KB

extern __shared__ __align__(1024) char gsm_raw[];

__global__ __launch_bounds__(256)
void gemm_mma(const __half* __restrict__ A, const __half* __restrict__ B,
              const float* __restrict__ bias, float* __restrict__ Cf,
              __half* __restrict__ Cs, int N, int split,
              unsigned* __restrict__ kmaxKey, int kmaxN,
              long sA, long sB, long sC)
{
    A += blockIdx.z * sA; B += blockIdx.z * sB;
    const int m0 = blockIdx.y * 128;
    const int n0 = blockIdx.x * 256;
    const uint32_t sbase = su32(gsm_raw);
    const int tid = threadIdx.x, wid = tid >> 5, lane = tid & 31;

    const __half* Arow = A + (long)m0 * K2;
    const __half* Brow = B + (long)n0 * K2;

    auto load_tile = [&](int kt, int s) {
        const uint32_t sa = sbase + s * STG_B;
        const uint32_t sb = sa + A_TILE_B;
        const __half* Ab = Arow + kt * 64;
        const __half* Bb = Brow + kt * 64;
#pragma unroll
        for (int it = 0; it < 12; it++) {
            int i = tid + it * 256;
            if (it < 4) {                        // A: i in [0,1024)
                int row = i >> 3, ch = (i & 7) * 16;
                CP16(sa + SW128(row * 128 + ch), Ab + (long)row * K2 + ch / 2);
            } else {                             // B: j in [0,2048)
                int j = i - 1024;
                int row = j >> 3, ch = (j & 7) * 16;
                CP16(sb + SW128(row * 128 + ch), Bb + (long)row * K2 + ch / 2);
            }
        }
    };

    float acc[4][8][4];
#pragma unroll
    for (int mf = 0; mf < 4; mf++)
#pragma unroll
        for (int nf = 0; nf < 8; nf++)
#pragma unroll
            for (int r = 0; r < 4; r++) acc[mf][nf][r] = 0.f;

    const int wm = wid >> 2, wn = wid & 3;
    const int a_row = wm * 64 + (lane & 15);                      // + mf*16
    const int a_sec = (lane >> 4) * 16;
    const int b_row = wn * 64 + (lane & 7) + ((lane >> 4) << 3);  // + nf2*16
    const int b_sec = ((lane >> 3) & 1) * 16;

    load_tile(0, 0); CP_COMMIT();

    for (int kt = 0; kt < GNK; kt++) {
        if (kt + 1 < GNK) { load_tile(kt + 1, (kt + 1) & 1); CP_COMMIT(); CP_WAIT(1); }
        else CP_WAIT(0);
        __syncthreads();

        const uint32_t sa = sbase + (kt & 1) * STG_B;
        const uint32_t sb = sa + A_TILE_B;
#pragma unroll
        for (int ks = 0; ks < 4; ks++) {
            uint32_t af[4][4], bf[8][2];
#pragma unroll
            for (int mf = 0; mf < 4; mf++)
                LDSM4(af[mf][0], af[mf][1], af[mf][2], af[mf][3],
                      sa + SW128((a_row + mf * 16) * 128 + ks * 32 + a_sec));
#pragma unroll
            for (int nf2 = 0; nf2 < 4; nf2++)
                LDSM4(bf[nf2 * 2][0], bf[nf2 * 2][1], bf[nf2 * 2 + 1][0], bf[nf2 * 2 + 1][1],
                      sb + SW128((b_row + nf2 * 16) * 128 + ks * 32 + b_sec));
#pragma unroll
            for (int nf = 0; nf < 8; nf++)
#pragma unroll
                for (int mf = 0; mf < 4; mf++)
                    MMA16816(acc[mf][nf], af[mf], bf[nf]);
        }
        __syncthreads();
    }

    // Epilogue
#pragma unroll
    for (int nf = 0; nf < 8; nf++) {
        const int col = n0 + wn * 64 + nf * 8 + (lane & 3) * 2;
        const float b0 = __ldg(bias + col), b1 = __ldg(bias + col + 1);
        float cm0 = -3.402823466e38f, cm1 = -3.402823466e38f;
#pragma unroll
        for (int mf = 0; mf < 4; mf++) {
            const int row = m0 + wm * 64 + mf * 16 + (lane >> 2);
            float v0 = acc[mf][nf][0] + b0, v1 = acc[mf][nf][1] + b1;
            float v2 = acc[mf][nf][2] + b0, v3 = acc[mf][nf][3] + b1;
            if (!split) {
                float* c0 = Cf + blockIdx.z * sC + (long)row * N + col;
                float2 p0; p0.x = v0; p0.y = v1; *(float2*)c0 = p0;
                float2 p1; p1.x = v2; p1.y = v3; *(float2*)(c0 + 8 * N) = p1;
            } else {
                __half h0 = __float2half_rn(v0), h1 = __float2half_rn(v1);
                __half h2 = __float2half_rn(v2), h3 = __float2half_rn(v3);
                __half l0 = __float2half_rn(v0 - __half2float(h0));
                __half l1 = __float2half_rn(v1 - __half2float(h1));
                __half l2 = __float2half_rn(v2 - __half2float(h2));
                __half l3 = __float2half_rn(v3 - __half2float(h3));
                __half* o0 = Cs + (long)row * K2 + col;
                __half* o1 = Cs + (long)(row + 8) * K2 + col;
                __half2 p;
                p.x = h0; p.y = h1; *(__half2*)o0 = p;
                p.x = l0; p.y = l1; *(__half2*)(o0 + DIM) = p;
                p.x = h2; p.y = h3; *(__half2*)o1 = p;
                p.x = l2; p.y = l3; *(__half2*)(o1 + DIM) = p;
            }
            cm0 = fmaxf(cm0, fmaxf(v0, v2));
            cm1 = fmaxf(cm1, fmaxf(v1, v3));
        }
        if (col < kmaxN) {       // uniform across warp (kmaxN multiple of 64)
#pragma unroll
            for (int sh = 4; sh < 32; sh <<= 1) {
                cm0 = fmaxf(cm0, __shfl_xor_sync(0xffffffffu, cm0, sh));
                cm1 = fmaxf(cm1, __shfl_xor_sync(0xffffffffu, cm1, sh));
            }
            if ((lane >> 2) == 0) {
                const int b_idx = m0 >> 12;     // 4096 rows per batch
                atomicMax(kmaxKey + b_idx * DIM + col, fkey(cm0));
                atomicMax(kmaxKey + b_idx * DIM + col + 1, fkey(cm1));
            }
        }
    }
}

// ---------------------------------------------------------------------------
// init: zero softmax accumulators (persisted device globals)
// ---------------------------------------------------------------------------
__global__ __launch_bounds__(256)
void init_stats()
{
    int i = blockIdx.x * 256 + threadIdx.x;
    if (i < BATCH * DIM) { g_kmaxKey[i] = 0u; g_Z[i] = 0.f; }
}

// ---------------------------------------------------------------------------
// split-fp16 conversions
// ---------------------------------------------------------------------------
// Activations: [M,1024] f32 -> [M,2048] fp16 as [hi | lo]
__global__ __launch_bounds__(256)
void split_act(const float* __restrict__ in, __half* __restrict__ out, long total4)
{
    for (long idx = blockIdx.x * 256L + threadIdx.x; idx < total4; idx += gridDim.x * 256L) {
        float4 v = ((const float4*)in)[idx];
        long m = idx >> 8;
        int c = (int)(idx & 255) * 4;
        __half h0 = __float2half_rn(v.x), h1 = __float2half_rn(v.y);
        __half h2 = __float2half_rn(v.z), h3 = __float2half_rn(v.w);
        __half l0 = __float2half_rn(v.x - __half2float(h0));
        __half l1 = __float2half_rn(v.y - __half2float(h1));
        __half l2 = __float2half_rn(v.z - __half2float(h2));
        __half l3 = __float2half_rn(v.w - __half2float(h3));
        __half* o = out + m * K2 + c;
        __half2 p;
        p.x = h0; p.y = h1; ((__half2*)o)[0] = p;
        p.x = h2; p.y = h3; ((__half2*)o)[1] = p;
        p.x = l0; p.y = l1; ((__half2*)(o + DIM))[0] = p;
        p.x = l2; p.y = l3; ((__half2*)(o + DIM))[1] = p;
    }
}

// Weights (transpose+split): in [1024,N] f32 -> out [N,2048] fp16 as [hi | hi]
__global__ __launch_bounds__(256)
void split_wt(const float* __restrict__ in, __half* __restrict__ out,
              int N, long sin, long sout)
{
    __shared__ float t[32][33];
    in += blockIdx.z * sin; out += blockIdx.z * sout;
    const int n0 = blockIdx.x * 32, k0 = blockIdx.y * 32;
    const int tx = threadIdx.x & 31, ty = threadIdx.x >> 5;
#pragma unroll
    for (int i = 0; i < 4; i++)
        t[ty + i * 8][tx] = in[(long)(k0 + ty + i * 8) * N + n0 + tx];
    __syncthreads();
#pragma unroll
    for (int i = 0; i < 4; i++) {
        const int nn = ty + i * 8;
        float v = t[tx][nn];
        __half hi = __float2half_rn(v);
        __half* o = out + (long)(n0 + nn) * K2 + k0 + tx;
        o[0] = hi; o[DIM] = hi;
    }
}

// ---------------------------------------------------------------------------
// Context partial with fused exp + Z accumulation.
// grid (64, 8): each block handles one (b,h) over a 512-timestep slice.
// ---------------------------------------------------------------------------
__global__ __launch_bounds__(256)
void context_part()
{
    const int bh = blockIdx.x;
    const int tc = blockIdx.y;
    const int b = bh >> 4;
    const int h = bh & 15;

    const float* kbase = g_kv + (long)b * TLEN * (2 * DIM) + h * HD;
    const float* vbase = kbase + DIM;

    __shared__ float ks[32][68];
    __shared__ float vs[32][68];
    __shared__ float kmaxs[64];
    __shared__ float sZ[64];

    const int tid = threadIdx.x;
    const int tx = tid & 15;
    const int ty = tid >> 4;

    if (tid < 64) {
        kmaxs[tid] = fdec(g_kmaxKey[b * DIM + h * HD + tid]);
        sZ[tid] = 0.f;
    }
    __syncthreads();

    const int c4 = (tid & 15) * 4;
    float4 km;
    km.x = kmaxs[c4]; km.y = kmaxs[c4 + 1]; km.z = kmaxs[c4 + 2]; km.w = kmaxs[c4 + 3];
    float z0 = 0.f, z1 = 0.f, z2 = 0.f, z3 = 0.f;

    float acc[4][4];
#pragma unroll
    for (int i = 0; i < 4; i++)
#pragma unroll
        for (int j = 0; j < 4; j++) acc[i][j] = 0.f;

    for (int t0 = tc * 512; t0 < tc * 512 + 512; t0 += 32) {
#pragma unroll
        for (int ii = 0; ii < 2; ii++) {
            const int i = tid + ii * 256;
            const int r = i >> 4;
            float4 kv4 = *(const float4*)(kbase + (long)(t0 + r) * (2 * DIM) + c4);
            float4 e;
            e.x = expf(kv4.x - km.x); e.y = expf(kv4.y - km.y);
            e.z = expf(kv4.z - km.z); e.w = expf(kv4.w - km.w);
            *(float4*)&ks[r][c4] = e;
            z0 += e.x; z1 += e.y; z2 += e.z; z3 += e.w;
            *(float4*)&vs[r][c4] = *(const float4*)(vbase + (long)(t0 + r) * (2 * DIM) + c4);
        }
        __syncthreads();
#pragma unroll 8
        for (int kk = 0; kk < 32; kk++) {
            float rd[4], rv[4];
#pragma unroll
            for (int i = 0; i < 4; i++) rd[i] = ks[kk][ty * 4 + i];
#pragma unroll
            for (int j = 0; j < 4; j++) rv[j] = vs[kk][tx * 4 + j];
#pragma unroll
            for (int i = 0; i < 4; i++)
#pragma unroll
                for (int j = 0; j < 4; j++)
                    acc[i][j] = fmaf(rd[i], rv[j], acc[i][j]);
        }
        __syncthreads();
    }

    atomicAdd(&sZ[c4], z0);
    atomicAdd(&sZ[c4 + 1], z1);
    atomicAdd(&sZ[c4 + 2], z2);
    atomicAdd(&sZ[c4 + 3], z3);

    float* out = g_Cp + ((long)bh * 8 + tc) * (HD * HD);
#pragma unroll
    for (int i = 0; i < 4; i++)
#pragma unroll
        for (int j = 0; j < 4; j++)
            out[(ty * 4 + i) * HD + tx * 4 + j] = acc[i][j];

    __syncthreads();
    if (tid < 64)
        atomicAdd(&g_Z[b * DIM + h * HD + tid], sZ[tid]);
}

__global__ __launch_bounds__(256)
void context_reduce()
{
    const int bh = blockIdx.x;
    const int b = bh >> 4, h = bh & 15;
    for (int i = threadIdx.x; i < HD * HD; i += 256) {
        float s = 0.f;
#pragma unroll
        for (int c = 0; c < 8; c++)
            s += g_Cp[((long)bh * 8 + c) * (HD * HD) + i];
        const int d = i >> 6;
        g_Cn[(long)bh * (HD * HD) + i] = s / g_Z[b * DIM + h * HD + d];
    }
}

// ---------------------------------------------------------------------------
// Expand: E_b[h*64+d][n] = sum_w Cn[b,h][d][w] * W_out[h*64+w][n]
// ---------------------------------------------------------------------------
__global__ __launch_bounds__(256)
void expand_kernel(const float* __restrict__ w_out)
{
    const int bh = blockIdx.y;
    const int b = bh >> 4;
    const int h = bh & 15;
    const int cb = blockIdx.x * 128;

    __shared__ float cs[64][64];
    __shared__ float ws[64][128];

    const int tid = threadIdx.x;
    for (int i = tid; i < 1024; i += 256) {
        const int r = i >> 4;
        const int c = (i & 15) * 4;
        *(float4*)&cs[r][c] = *(const float4*)(g_Cn + (long)bh * 4096 + r * 64 + c);
    }
    for (int i = tid; i < 2048; i += 256) {
        const int r = i >> 5;
        const int c = (i & 31) * 4;
        *(float4*)&ws[r][c] = *(const float4*)(w_out + (long)(h * HD + r) * DIM + cb + c);
    }
    __syncthreads();

    const int tx = tid & 31;
    const int ty = tid >> 5;

    float acc[8][4];
#pragma unroll
    for (int rr = 0; rr < 8; rr++)
#pragma unroll
        for (int j = 0; j < 4; j++) acc[rr][j] = 0.f;

#pragma unroll 4
    for (int w = 0; w < 64; w++) {
        float4 wv = *(float4*)&ws[w][tx * 4];
#pragma unroll
        for (int rr = 0; rr < 8; rr++) {
            const float cv = cs[ty + rr * 8][w];
            acc[rr][0] = fmaf(cv, wv.x, acc[rr][0]);
            acc[rr][1] = fmaf(cv, wv.y, acc[rr][1]);
            acc[rr][2] = fmaf(cv, wv.z, acc[rr][2]);
            acc[rr][3] = fmaf(cv, wv.w, acc[rr][3]);
        }
    }

#pragma unroll
    for (int rr = 0; rr < 8; rr++) {
        const int row = ty + rr * 8;
        float4 o; o.x = acc[rr][0]; o.y = acc[rr][1]; o.z = acc[rr][2]; o.w = acc[rr][3];
        *(float4*)(g_E + ((long)b * DIM + h * HD + row) * DIM + cb + tx * 4) = o;
    }
}

// ---------------------------------------------------------------------------
extern "C" void kernel_launch(void* const* d_in, const int* in_sizes, int n_in,
                              void* d_out, int out_size)
{
    const float* x     = (const float*)d_in[0];
    const float* z     = (const float*)d_in[1];
    const float* w_q   = (const float*)d_in[2];
    const float* b_q   = (const float*)d_in[3];
    const float* w_kv  = (const float*)d_in[4];
    const float* b_kv  = (const float*)d_in[5];
    const float* w_out = (const float*)d_in[6];
    const float* b_out = (const float*)d_in[7];
    float* out = (float*)d_out;

    float *kv, *E;
    unsigned* kmaxKey;
    __half *zs, *xs, *qs, *wkvs, *wqs, *Es;
    cudaGetSymbolAddress((void**)&kv, g_kv);
    cudaGetSymbolAddress((void**)&E, g_E);
    cudaGetSymbolAddress((void**)&kmaxKey, g_kmaxKey);
    cudaGetSymbolAddress((void**)&zs, g_zs);
    cudaGetSymbolAddress((void**)&xs, g_xs);
    cudaGetSymbolAddress((void**)&qs, g_qs);
    cudaGetSymbolAddress((void**)&wkvs, g_wkvs);
    cudaGetSymbolAddress((void**)&wqs, g_wqs);
    cudaGetSymbolAddress((void**)&Es, g_Es);

    cudaFuncSetAttribute(gemm_mma, cudaFuncAttributeMaxDynamicSharedMemorySize, GSMEM);

    const int M = BATCH * TLEN;          // 16384
    const long tot4 = (long)M * DIM / 4;

    // 0. zero softmax accumulators (device globals persist across replays)
    init_stats<<<16, 256>>>();
    // 1. weight splits
    { dim3 g(2 * DIM / 32, DIM / 32, 1); split_wt<<<g, 256>>>(w_kv, wkvs, 2 * DIM, 0, 0); }
    { dim3 g(DIM / 32, DIM / 32, 1);     split_wt<<<g, 256>>>(w_q, wqs, DIM, 0, 0); }
    // 2. activation splits
    split_act<<<2048, 256>>>(z, zs, tot4);
    split_act<<<2048, 256>>>(x, xs, tot4);
    // 3. kv = z @ w_kv + b_kv  (fp32 out; fused per-(b,col) max of k half)
    { dim3 g(2 * DIM / 256, M / 128, 1);
      gemm_mma<<<g, 256, GSMEM>>>(zs, wkvs, b_kv, kv, nullptr, 2 * DIM, 0,
                                  kmaxKey, DIM, 0, 0, 0); }
    // 4. q = x @ w_q + b_q  (split-fp16 out straight into g_qs)
    { dim3 g(DIM / 256, M / 128, 1);
      gemm_mma<<<g, 256, GSMEM>>>(xs, wqs, b_q, nullptr, qs, DIM, 1,
                                  kmaxKey, 0, 0, 0, 0); }
    // 5. context (fused exp + Z; partials over T, then reduce+normalize)
    { dim3 g(BATCH * NH, 8); context_part<<<g, 256>>>(); }
    context_reduce<<<BATCH * NH, 256>>>();
    // 6. E_b = blockdiag(Cn) @ W_out
    { dim3 g(DIM / 128, BATCH * NH); expand_kernel<<<g, 256>>>(w_out); }
    // 7. split E (batched transpose, [hi|hi])
    { dim3 g(DIM / 32, DIM / 32, BATCH); split_wt<<<g, 256>>>(E, Es, DIM, (long)DIM * DIM, (long)DIM * K2); }
    // 8. out_b = q_b @ E_b + b_out (batched, fp32 out)
    { dim3 g(DIM / 256, TLEN / 128, BATCH);
      gemm_mma<<<g, 256, GSMEM>>>(qs, Es, b_out, out, nullptr, DIM, 0,
                                  kmaxKey, 0, (long)TLEN * K2, (long)DIM * K2, (long)TLEN * DIM); }
}

// round 7
// speedup vs baseline: 1.6412x; 1.2221x over previous
#include <cuda_runtime.h>
#include <cuda_fp16.h>
#include <cstdint>

// Problem constants
#define BATCH 4
#define TLEN  4096
#define DIM   1024
#define NH    16
#define HD    64
#define K2    2048           // A-side split-fp16 width [hi|lo]
#define TSPL  16             // context T-slices

// ---------------------------------------------------------------------------
// Scratch (device globals; no allocation allowed)
// ---------------------------------------------------------------------------
__device__ static __align__(256) float g_kv[BATCH * TLEN * 2 * DIM];   // 128 MB
__device__ static __align__(256) float g_Z [BATCH * DIM];
__device__ static __align__(256) unsigned g_kmaxKey[BATCH * DIM];
__device__ static __align__(256) float g_Cp[BATCH * NH * TSPL * HD * HD];
__device__ static __align__(256) float g_Cn[BATCH * NH * HD * HD];
__device__ static __align__(256) float g_E [BATCH * DIM * DIM];        // 16 MB

__device__ static __align__(256) __half g_zs [(long)BATCH * TLEN * K2]; // 67 MB
__device__ static __align__(256) __half g_xs [(long)BATCH * TLEN * K2];
__device__ static __align__(256) __half g_qs [(long)BATCH * TLEN * K2];
__device__ static __align__(256) __half g_wkvs[(long)2 * DIM * DIM];    // hi only
__device__ static __align__(256) __half g_wqs [(long)DIM * DIM];
__device__ static __align__(256) __half g_Es  [(long)BATCH * DIM * DIM];

// ---------------------------------------------------------------------------
// Helpers
// ---------------------------------------------------------------------------
#define SW128(o) ((o) ^ (((o) >> 3) & 0x70))

static __device__ __forceinline__ uint32_t su32(const void* p) {
    uint32_t a;
    asm("{ .reg .u64 t; cvta.to.shared.u64 t, %1; cvt.u32.u64 %0, t; }" : "=r"(a) : "l"(p));
    return a;
}

// monotone float <-> unsigned key (for atomicMax over floats)
static __device__ __forceinline__ unsigned fkey(float f) {
    unsigned i = __float_as_uint(f);
    return (i & 0x80000000u) ? ~i : (i | 0x80000000u);
}
static __device__ __forceinline__ float fdec(unsigned k) {
    unsigned i = (k & 0x80000000u) ? (k & 0x7FFFFFFFu) : ~k;
    return __uint_as_float(i);
}

#define CP16(dst, src)   asm volatile("cp.async.cg.shared.global [%0], [%1], 16;" :: "r"(dst), "l"(src))
#define CP_COMMIT()      asm volatile("cp.async.commit_group;" ::: "memory")
#define CP_WAIT(n)       asm volatile("cp.async.wait_group %0;" :: "n"(n) : "memory")

#define LDSM4(r0, r1, r2, r3, addr) \
    asm volatile("ldmatrix.sync.aligned.m8n8.x4.shared.b16 {%0,%1,%2,%3}, [%4];" \
        : "=r"(r0), "=r"(r1), "=r"(r2), "=r"(r3) : "r"(addr))

#define MMA16816(d, a, b) \
    asm volatile("mma.sync.aligned.m16n8k16.row.col.f32.f16.f16.f32 " \
        "{%0,%1,%2,%3},{%4,%5,%6,%7},{%8,%9},{%0,%1,%2,%3};" \
        : "+f"((d)[0]), "+f"((d)[1]), "+f"((d)[2]), "+f"((d)[3]) \
        : "r"((a)[0]), "r"((a)[1]), "r"((a)[2]), "r"((a)[3]), "r"((b)[0]), "r"((b)[1]))

// ---------------------------------------------------------------------------
// mma.sync fp16 GEMM:  C[M,N] = (A_hi + A_lo)[M,1024] * B_hi[N,1024]^T + bias
// A stored [M, 2048] = [hi|lo]; B stored [N, 1024] hi-only.
// BM=64, BN=256, BK=64, stage = {Ah 8K, Al 8K, B 32K} = 48 KB, 2 stages,
// 8 warps, warp tile 64x32, both A halves share one B tile.
// split=1: write split-fp16 [hi|lo] rows of width K2 into Cs.
// kmaxN>0: per-(batch,col) atomicMax of output (cols < kmaxN) into kmaxKey.
// grid = (N/256, M/64, batch)
// ---------------------------------------------------------------------------
#define GNK      16                 // 1024 / 64
#define AH_OFF   0
#define AL_OFF   8192
#define BB_OFF   16384
#define STG_B    49152              // 48 KB
#define GSMEM    (2 * STG_B)        // 96 KB

extern __shared__ __align__(1024) char gsm_raw[];

__global__ __launch_bounds__(256, 2)
void gemm_mma(const __half* __restrict__ A, const __half* __restrict__ B,
              const float* __restrict__ bias, float* __restrict__ Cf,
              __half* __restrict__ Cs, int N, int split,
              unsigned* __restrict__ kmaxKey, int kmaxN,
              long sA, long sB, long sC)
{
    A += blockIdx.z * sA; B += blockIdx.z * sB;
    const int m0 = blockIdx.y * 64;
    const int n0 = blockIdx.x * 256;
    const uint32_t sbase = su32(gsm_raw);
    const int tid = threadIdx.x, wid = tid >> 5, lane = tid & 31;

    const __half* Arow = A + (long)m0 * K2;       // rows stride K2
    const __half* Brow = B + (long)n0 * DIM;      // rows stride 1024

    auto load_tile = [&](int kt, int s) {
        const uint32_t st = sbase + s * STG_B;
        const int kc = kt * 64;                    // k-column base
#pragma unroll
        for (int it = 0; it < 12; it++) {
            int i = tid + it * 256;
            if (it < 2) {                          // A_hi: i in [0,512)
                int row = i >> 3, ch = (i & 7) * 16;
                CP16(st + AH_OFF + SW128(row * 128 + ch),
                     Arow + (long)row * K2 + kc + ch / 2);
            } else if (it < 4) {                   // A_lo
                int j = i - 512;
                int row = j >> 3, ch = (j & 7) * 16;
                CP16(st + AL_OFF + SW128(row * 128 + ch),
                     Arow + (long)row * K2 + DIM + kc + ch / 2);
            } else {                               // B: j in [0,2048)
                int j = i - 1024;
                int row = j >> 3, ch = (j & 7) * 16;
                CP16(st + BB_OFF + SW128(row * 128 + ch),
                     Brow + (long)row * DIM + kc + ch / 2);
            }
        }
    };

    float acc[4][4][4];
#pragma unroll
    for (int mf = 0; mf < 4; mf++)
#pragma unroll
        for (int nf = 0; nf < 4; nf++)
#pragma unroll
            for (int r = 0; r < 4; r++) acc[mf][nf][r] = 0.f;

    const int wn = wid;                                           // 0..7
    const int a_row = (lane & 15);                                // + mf*16
    const int a_sec = (lane >> 4) * 16;
    const int b_row = wn * 32 + (lane & 7) + ((lane >> 4) << 3);  // + nf2*16
    const int b_sec = ((lane >> 3) & 1) * 16;

    load_tile(0, 0); CP_COMMIT();

    for (int kt = 0; kt < GNK; kt++) {
        if (kt + 1 < GNK) { load_tile(kt + 1, (kt + 1) & 1); CP_COMMIT(); CP_WAIT(1); }
        else CP_WAIT(0);
        __syncthreads();

        const uint32_t st = sbase + (kt & 1) * STG_B;
#pragma unroll
        for (int ks = 0; ks < 4; ks++) {
            uint32_t bf[4][2];
#pragma unroll
            for (int nf2 = 0; nf2 < 2; nf2++)
                LDSM4(bf[nf2 * 2][0], bf[nf2 * 2][1], bf[nf2 * 2 + 1][0], bf[nf2 * 2 + 1][1],
                      st + BB_OFF + SW128((b_row + nf2 * 16) * 128 + ks * 32 + b_sec));
#pragma unroll
            for (int mf = 0; mf < 4; mf++) {
                uint32_t ah[4], al[4];
                const uint32_t arow_off = (a_row + mf * 16) * 128 + ks * 32 + a_sec;
                LDSM4(ah[0], ah[1], ah[2], ah[3], st + AH_OFF + SW128(arow_off));
                LDSM4(al[0], al[1], al[2], al[3], st + AL_OFF + SW128(arow_off));
#pragma unroll
                for (int nf = 0; nf < 4; nf++) {
                    MMA16816(acc[mf][nf], ah, bf[nf]);
                    MMA16816(acc[mf][nf], al, bf[nf]);
                }
            }
        }
        __syncthreads();
    }

    // Epilogue
#pragma unroll
    for (int nf = 0; nf < 4; nf++) {
        const int col = n0 + wn * 32 + nf * 8 + (lane & 3) * 2;
        const float b0 = __ldg(bias + col), b1 = __ldg(bias + col + 1);
        float cm0 = -3.402823466e38f, cm1 = -3.402823466e38f;
#pragma unroll
        for (int mf = 0; mf < 4; mf++) {
            const int row = m0 + mf * 16 + (lane >> 2);
            float v0 = acc[mf][nf][0] + b0, v1 = acc[mf][nf][1] + b1;
            float v2 = acc[mf][nf][2] + b0, v3 = acc[mf][nf][3] + b1;
            if (!split) {
                float* c0 = Cf + blockIdx.z * sC + (long)row * N + col;
                float2 p0; p0.x = v0; p0.y = v1; *(float2*)c0 = p0;
                float2 p1; p1.x = v2; p1.y = v3; *(float2*)(c0 + 8 * N) = p1;
            } else {
                __half h0 = __float2half_rn(v0), h1 = __float2half_rn(v1);
                __half h2 = __float2half_rn(v2), h3 = __float2half_rn(v3);
                __half l0 = __float2half_rn(v0 - __half2float(h0));
                __half l1 = __float2half_rn(v1 - __half2float(h1));
                __half l2 = __float2half_rn(v2 - __half2float(h2));
                __half l3 = __float2half_rn(v3 - __half2float(h3));
                __half* o0 = Cs + (long)row * K2 + col;
                __half* o1 = Cs + (long)(row + 8) * K2 + col;
                __half2 p;
                p.x = h0; p.y = h1; *(__half2*)o0 = p;
                p.x = l0; p.y = l1; *(__half2*)(o0 + DIM) = p;
                p.x = h2; p.y = h3; *(__half2*)o1 = p;
                p.x = l2; p.y = l3; *(__half2*)(o1 + DIM) = p;
            }
            cm0 = fmaxf(cm0, fmaxf(v0, v2));
            cm1 = fmaxf(cm1, fmaxf(v1, v3));
        }
        if (col < kmaxN) {       // uniform across warp (kmaxN multiple of 32)
#pragma unroll
            for (int sh = 4; sh < 32; sh <<= 1) {
                cm0 = fmaxf(cm0, __shfl_xor_sync(0xffffffffu, cm0, sh));
                cm1 = fmaxf(cm1, __shfl_xor_sync(0xffffffffu, cm1, sh));
            }
            if ((lane >> 2) == 0) {
                const int b_idx = m0 >> 12;     // 4096 rows per batch
                atomicMax(kmaxKey + b_idx * DIM + col, fkey(cm0));
                atomicMax(kmaxKey + b_idx * DIM + col + 1, fkey(cm1));
            }
        }
    }
}

// ---------------------------------------------------------------------------
// init: zero softmax accumulators (persisted device globals)
// ---------------------------------------------------------------------------
__global__ __launch_bounds__(256)
void init_stats()
{
    int i = blockIdx.x * 256 + threadIdx.x;
    if (i < BATCH * DIM) { g_kmaxKey[i] = 0u; g_Z[i] = 0.f; }
}

// ---------------------------------------------------------------------------
// split-fp16 conversions
// ---------------------------------------------------------------------------
// Activations: [M,1024] f32 -> [M,2048] fp16 as [hi | lo]
__global__ __launch_bounds__(256)
void split_act(const float* __restrict__ in, __half* __restrict__ out, long total4)
{
    for (long idx = blockIdx.x * 256L + threadIdx.x; idx < total4; idx += gridDim.x * 256L) {
        float4 v = ((const float4*)in)[idx];
        long m = idx >> 8;
        int c = (int)(idx & 255) * 4;
        __half h0 = __float2half_rn(v.x), h1 = __float2half_rn(v.y);
        __half h2 = __float2half_rn(v.z), h3 = __float2half_rn(v.w);
        __half l0 = __float2half_rn(v.x - __half2float(h0));
        __half l1 = __float2half_rn(v.y - __half2float(h1));
        __half l2 = __float2half_rn(v.z - __half2float(h2));
        __half l3 = __float2half_rn(v.w - __half2float(h3));
        __half* o = out + m * K2 + c;
        __half2 p;
        p.x = h0; p.y = h1; ((__half2*)o)[0] = p;
        p.x = h2; p.y = h3; ((__half2*)o)[1] = p;
        p.x = l0; p.y = l1; ((__half2*)(o + DIM))[0] = p;
        p.x = l2; p.y = l3; ((__half2*)(o + DIM))[1] = p;
    }
}

// Weights (transpose, hi only): in [1024,N] f32 -> out [N,1024] fp16
__global__ __launch_bounds__(256)
void split_wt(const float* __restrict__ in, __half* __restrict__ out,
              int N, long sin, long sout)
{
    __shared__ float t[32][33];
    in += blockIdx.z * sin; out += blockIdx.z * sout;
    const int n0 = blockIdx.x * 32, k0 = blockIdx.y * 32;
    const int tx = threadIdx.x & 31, ty = threadIdx.x >> 5;
#pragma unroll
    for (int i = 0; i < 4; i++)
        t[ty + i * 8][tx] = in[(long)(k0 + ty + i * 8) * N + n0 + tx];
    __syncthreads();
#pragma unroll
    for (int i = 0; i < 4; i++) {
        const int nn = ty + i * 8;
        out[(long)(n0 + nn) * DIM + k0 + tx] = __float2half_rn(t[tx][nn]);
    }
}

// ---------------------------------------------------------------------------
// Context partial with fused exp + Z accumulation.
// grid (64, TSPL): each block: one (b,h) over a 256-timestep slice.
// ---------------------------------------------------------------------------
__global__ __launch_bounds__(256)
void context_part()
{
    const int bh = blockIdx.x;
    const int tc = blockIdx.y;
    const int b = bh >> 4;
    const int h = bh & 15;

    const float* kbase = g_kv + (long)b * TLEN * (2 * DIM) + h * HD;
    const float* vbase = kbase + DIM;

    __shared__ float ks[32][68];
    __shared__ float vs[32][68];
    __shared__ float kmaxs[64];
    __shared__ float sZ[64];

    const int tid = threadIdx.x;
    const int tx = tid & 15;
    const int ty = tid >> 4;

    if (tid < 64) {
        kmaxs[tid] = fdec(g_kmaxKey[b * DIM + h * HD + tid]);
        sZ[tid] = 0.f;
    }
    __syncthreads();

    const int c4 = (tid & 15) * 4;
    float4 km;
    km.x = kmaxs[c4]; km.y = kmaxs[c4 + 1]; km.z = kmaxs[c4 + 2]; km.w = kmaxs[c4 + 3];
    float z0 = 0.f, z1 = 0.f, z2 = 0.f, z3 = 0.f;

    float acc[4][4];
#pragma unroll
    for (int i = 0; i < 4; i++)
#pragma unroll
        for (int j = 0; j < 4; j++) acc[i][j] = 0.f;

    const int tspan = TLEN / TSPL;    // 256
    for (int t0 = tc * tspan; t0 < tc * tspan + tspan; t0 += 32) {
#pragma unroll
        for (int ii = 0; ii < 2; ii++) {
            const int i = tid + ii * 256;
            const int r = i >> 4;
            float4 kv4 = *(const float4*)(kbase + (long)(t0 + r) * (2 * DIM) + c4);
            float4 e;
            e.x = expf(kv4.x - km.x); e.y = expf(kv4.y - km.y);
            e.z = expf(kv4.z - km.z); e.w = expf(kv4.w - km.w);
            *(float4*)&ks[r][c4] = e;
            z0 += e.x; z1 += e.y; z2 += e.z; z3 += e.w;
            *(float4*)&vs[r][c4] = *(const float4*)(vbase + (long)(t0 + r) * (2 * DIM) + c4);
        }
        __syncthreads();
#pragma unroll 8
        for (int kk = 0; kk < 32; kk++) {
            float rd[4], rv[4];
#pragma unroll
            for (int i = 0; i < 4; i++) rd[i] = ks[kk][ty * 4 + i];
#pragma unroll
            for (int j = 0; j < 4; j++) rv[j] = vs[kk][tx * 4 + j];
#pragma unroll
            for (int i = 0; i < 4; i++)
#pragma unroll
                for (int j = 0; j < 4; j++)
                    acc[i][j] = fmaf(rd[i], rv[j], acc[i][j]);
        }
        __syncthreads();
    }

    atomicAdd(&sZ[c4], z0);
    atomicAdd(&sZ[c4 + 1], z1);
    atomicAdd(&sZ[c4 + 2], z2);
    atomicAdd(&sZ[c4 + 3], z3);

    float* out = g_Cp + ((long)bh * TSPL + tc) * (HD * HD);
#pragma unroll
    for (int i = 0; i < 4; i++)
#pragma unroll
        for (int j = 0; j < 4; j++)
            out[(ty * 4 + i) * HD + tx * 4 + j] = acc[i][j];

    __syncthreads();
    if (tid < 64)
        atomicAdd(&g_Z[b * DIM + h * HD + tid], sZ[tid]);
}

__global__ __launch_bounds__(256)
void context_reduce()
{
    const int bh = blockIdx.x;
    const int b = bh >> 4, h = bh & 15;
    for (int i = threadIdx.x; i < HD * HD; i += 256) {
        float s = 0.f;
#pragma unroll
        for (int c = 0; c < TSPL; c++)
            s += g_Cp[((long)bh * TSPL + c) * (HD * HD) + i];
        const int d = i >> 6;
        g_Cn[(long)bh * (HD * HD) + i] = s / g_Z[b * DIM + h * HD + d];
    }
}

// ---------------------------------------------------------------------------
// Expand: E_b[h*64+d][n] = sum_w Cn[b,h][d][w] * W_out[h*64+w][n]
// ---------------------------------------------------------------------------
__global__ __launch_bounds__(256)
void expand_kernel(const float* __restrict__ w_out)
{
    const int bh = blockIdx.y;
    const int b = bh >> 4;
    const int h = bh & 15;
    const int cb = blockIdx.x * 128;

    __shared__ float cs[64][64];
    __shared__ float ws[64][128];

    const int tid = threadIdx.x;
    for (int i = tid; i < 1024; i += 256) {
        const int r = i >> 4;
        const int c = (i & 15) * 4;
        *(float4*)&cs[r][c] = *(const float4*)(g_Cn + (long)bh * 4096 + r * 64 + c);
    }
    for (int i = tid; i < 2048; i += 256) {
        const int r = i >> 5;
        const int c = (i & 31) * 4;
        *(float4*)&ws[r][c] = *(const float4*)(w_out + (long)(h * HD + r) * DIM + cb + c);
    }
    __syncthreads();

    const int tx = tid & 31;
    const int ty = tid >> 5;

    float acc[8][4];
#pragma unroll
    for (int rr = 0; rr < 8; rr++)
#pragma unroll
        for (int j = 0; j < 4; j++) acc[rr][j] = 0.f;

#pragma unroll 4
    for (int w = 0; w < 64; w++) {
        float4 wv = *(float4*)&ws[w][tx * 4];
#pragma unroll
        for (int rr = 0; rr < 8; rr++) {
            const float cv = cs[ty + rr * 8][w];
            acc[rr][0] = fmaf(cv, wv.x, acc[rr][0]);
            acc[rr][1] = fmaf(cv, wv.y, acc[rr][1]);
            acc[rr][2] = fmaf(cv, wv.z, acc[rr][2]);
            acc[rr][3] = fmaf(cv, wv.w, acc[rr][3]);
        }
    }

#pragma unroll
    for (int rr = 0; rr < 8; rr++) {
        const int row = ty + rr * 8;
        float4 o; o.x = acc[rr][0]; o.y = acc[rr][1]; o.z = acc[rr][2]; o.w = acc[rr][3];
        *(float4*)(g_E + ((long)b * DIM + h * HD + row) * DIM + cb + tx * 4) = o;
    }
}

// ---------------------------------------------------------------------------
extern "C" void kernel_launch(void* const* d_in, const int* in_sizes, int n_in,
                              void* d_out, int out_size)
{
    const float* x     = (const float*)d_in[0];
    const float* z     = (const float*)d_in[1];
    const float* w_q   = (const float*)d_in[2];
    const float* b_q   = (const float*)d_in[3];
    const float* w_kv  = (const float*)d_in[4];
    const float* b_kv  = (const float*)d_in[5];
    const float* w_out = (const float*)d_in[6];
    const float* b_out = (const float*)d_in[7];
    float* out = (float*)d_out;

    float *kv, *E;
    unsigned* kmaxKey;
    __half *zs, *xs, *qs, *wkvs, *wqs, *Es;
    cudaGetSymbolAddress((void**)&kv, g_kv);
    cudaGetSymbolAddress((void**)&E, g_E);
    cudaGetSymbolAddress((void**)&kmaxKey, g_kmaxKey);
    cudaGetSymbolAddress((void**)&zs, g_zs);
    cudaGetSymbolAddress((void**)&xs, g_xs);
    cudaGetSymbolAddress((void**)&qs, g_qs);
    cudaGetSymbolAddress((void**)&wkvs, g_wkvs);
    cudaGetSymbolAddress((void**)&wqs, g_wqs);
    cudaGetSymbolAddress((void**)&Es, g_Es);

    cudaFuncSetAttribute(gemm_mma, cudaFuncAttributeMaxDynamicSharedMemorySize, GSMEM);

    const int M = BATCH * TLEN;          // 16384
    const long tot4 = (long)M * DIM / 4;

    // 0. zero softmax accumulators (device globals persist across replays)
    init_stats<<<16, 256>>>();
    // 1. weight transposes (hi only)
    { dim3 g(2 * DIM / 32, DIM / 32, 1); split_wt<<<g, 256>>>(w_kv, wkvs, 2 * DIM, 0, 0); }
    { dim3 g(DIM / 32, DIM / 32, 1);     split_wt<<<g, 256>>>(w_q, wqs, DIM, 0, 0); }
    // 2. activation splits
    split_act<<<2048, 256>>>(z, zs, tot4);
    split_act<<<2048, 256>>>(x, xs, tot4);
    // 3. kv = z @ w_kv + b_kv  (fp32 out; fused per-(b,col) max of k half)
    { dim3 g(2 * DIM / 256, M / 64, 1);
      gemm_mma<<<g, 256, GSMEM>>>(zs, wkvs, b_kv, kv, nullptr, 2 * DIM, 0,
                                  kmaxKey, DIM, 0, 0, 0); }
    // 4. q = x @ w_q + b_q  (split-fp16 out straight into g_qs)
    { dim3 g(DIM / 256, M / 64, 1);
      gemm_mma<<<g, 256, GSMEM>>>(xs, wqs, b_q, nullptr, qs, DIM, 1,
                                  kmaxKey, 0, 0, 0, 0); }
    // 5. context (fused exp + Z; partials over T, then reduce+normalize)
    { dim3 g(BATCH * NH, TSPL); context_part<<<g, 256>>>(); }
    context_reduce<<<BATCH * NH, 256>>>();
    // 6. E_b = blockdiag(Cn) @ W_out
    { dim3 g(DIM / 128, BATCH * NH); expand_kernel<<<g, 256>>>(w_out); }
    // 7. E transpose (batched, hi only)
    { dim3 g(DIM / 32, DIM / 32, BATCH); split_wt<<<g, 256>>>(E, Es, DIM, (long)DIM * DIM, (long)DIM * DIM); }
    // 8. out_b = q_b @ E_b + b_out (batched, fp32 out)
    { dim3 g(DIM / 256, TLEN / 64, BATCH);
      gemm_mma<<<g, 256, GSMEM>>>(qs, Es, b_out, out, nullptr, DIM, 0,
                                  kmaxKey, 0, (long)TLEN * K2, (long)DIM * DIM, (long)TLEN * DIM); }
}

// round 8
// speedup vs baseline: 2.4690x; 1.5043x over previous
#include <cuda_runtime.h>
#include <cuda_fp16.h>
#include <cstdint>

// Problem constants
#define BATCH 4
#define TLEN  4096
#define DIM   1024
#define NH    16
#define HD    64
#define TSPL  16             // context T-slices

// ---------------------------------------------------------------------------
// Scratch (device globals; no allocation allowed)
// ---------------------------------------------------------------------------
__device__ static __align__(256) float g_kv[BATCH * TLEN * 2 * DIM];   // 128 MB
__device__ static __align__(256) float g_Z [BATCH * DIM];
__device__ static __align__(256) unsigned g_kmaxKey[BATCH * DIM];
__device__ static __align__(256) float g_Cp[BATCH * NH * TSPL * HD * HD];
__device__ static __align__(256) float g_Cn[BATCH * NH * HD * HD];
__device__ static __align__(256) float g_E [BATCH * DIM * DIM];        // 16 MB

__device__ static __align__(256) __half g_zs [(long)BATCH * TLEN * DIM]; // 33.6 MB
__device__ static __align__(256) __half g_xs [(long)BATCH * TLEN * DIM];
__device__ static __align__(256) __half g_qs [(long)BATCH * TLEN * DIM];
__device__ static __align__(256) __half g_wkvs[(long)2 * DIM * DIM];
__device__ static __align__(256) __half g_wqs [(long)DIM * DIM];
__device__ static __align__(256) __half g_Es  [(long)BATCH * DIM * DIM];

// ---------------------------------------------------------------------------
// Helpers
// ---------------------------------------------------------------------------
#define SW128(o) ((o) ^ (((o) >> 3) & 0x70))

static __device__ __forceinline__ uint32_t su32(const void* p) {
    uint32_t a;
    asm("{ .reg .u64 t; cvta.to.shared.u64 t, %1; cvt.u32.u64 %0, t; }" : "=r"(a) : "l"(p));
    return a;
}

// monotone float <-> unsigned key (for atomicMax over floats)
static __device__ __forceinline__ unsigned fkey(float f) {
    unsigned i = __float_as_uint(f);
    return (i & 0x80000000u) ? ~i : (i | 0x80000000u);
}
static __device__ __forceinline__ float fdec(unsigned k) {
    unsigned i = (k & 0x80000000u) ? (k & 0x7FFFFFFFu) : ~k;
    return __uint_as_float(i);
}

#define CP16(dst, src)   asm volatile("cp.async.cg.shared.global [%0], [%1], 16;" :: "r"(dst), "l"(src))
#define CP_COMMIT()      asm volatile("cp.async.commit_group;" ::: "memory")
#define CP_WAIT(n)       asm volatile("cp.async.wait_group %0;" :: "n"(n) : "memory")

#define LDSM4(r0, r1, r2, r3, addr) \
    asm volatile("ldmatrix.sync.aligned.m8n8.x4.shared.b16 {%0,%1,%2,%3}, [%4];" \
        : "=r"(r0), "=r"(r1), "=r"(r2), "=r"(r3) : "r"(addr))

#define MMA16816(d, a, b) \
    asm volatile("mma.sync.aligned.m16n8k16.row.col.f32.f16.f16.f32 " \
        "{%0,%1,%2,%3},{%4,%5,%6,%7},{%8,%9},{%0,%1,%2,%3};" \
        : "+f"((d)[0]), "+f"((d)[1]), "+f"((d)[2]), "+f"((d)[3]) \
        : "r"((a)[0]), "r"((a)[1]), "r"((a)[2]), "r"((a)[3]), "r"((b)[0]), "r"((b)[1]))

// ---------------------------------------------------------------------------
// mma.sync fp16 GEMM:  C[M,N] = A[M,1024] * B[N,1024]^T + bias   (both hi fp16)
// BM=64, BN=256, BK=64, stage = {A 8K, B 32K} = 40 KB, 2 stages (80 KB),
// 8 warps, warp tile 64x32, 2 CTAs/SM.
// split=1: write fp16 rows (width DIM) into Cs.
// kmaxN>0: per-(batch,col) atomicMax of output (cols < kmaxN) into kmaxKey.
// grid = (N/256, M/64, batch)
// ---------------------------------------------------------------------------
#define GNK      16                 // 1024 / 64
#define AH_OFF   0
#define BB_OFF   8192
#define STG_B    40960              // 40 KB
#define GSMEM    (2 * STG_B)        // 80 KB

extern __shared__ __align__(1024) char gsm_raw[];

__global__ __launch_bounds__(256, 2)
void gemm_mma(const __half* __restrict__ A, const __half* __restrict__ B,
              const float* __restrict__ bias, float* __restrict__ Cf,
              __half* __restrict__ Cs, int N, int split,
              unsigned* __restrict__ kmaxKey, int kmaxN,
              long sA, long sB, long sC)
{
    A += blockIdx.z * sA; B += blockIdx.z * sB;
    const int m0 = blockIdx.y * 64;
    const int n0 = blockIdx.x * 256;
    const uint32_t sbase = su32(gsm_raw);
    const int tid = threadIdx.x, wid = tid >> 5, lane = tid & 31;

    const __half* Arow = A + (long)m0 * DIM;
    const __half* Brow = B + (long)n0 * DIM;

    auto load_tile = [&](int kt, int s) {
        const uint32_t st = sbase + s * STG_B;
        const int kc = kt * 64;
#pragma unroll
        for (int it = 0; it < 10; it++) {
            int i = tid + it * 256;
            if (it < 2) {                          // A: i in [0,512)
                int row = i >> 3, ch = (i & 7) * 16;
                CP16(st + AH_OFF + SW128(row * 128 + ch),
                     Arow + (long)row * DIM + kc + ch / 2);
            } else {                               // B: j in [0,2048)
                int j = i - 512;
                int row = j >> 3, ch = (j & 7) * 16;
                CP16(st + BB_OFF + SW128(row * 128 + ch),
                     Brow + (long)row * DIM + kc + ch / 2);
            }
        }
    };

    float acc[4][4][4];
#pragma unroll
    for (int mf = 0; mf < 4; mf++)
#pragma unroll
        for (int nf = 0; nf < 4; nf++)
#pragma unroll
            for (int r = 0; r < 4; r++) acc[mf][nf][r] = 0.f;

    const int wn = wid;                                           // 0..7
    const int a_row = (lane & 15);                                // + mf*16
    const int a_sec = (lane >> 4) * 16;
    const int b_row = wn * 32 + (lane & 7) + ((lane >> 4) << 3);  // + nf2*16
    const int b_sec = ((lane >> 3) & 1) * 16;

    load_tile(0, 0); CP_COMMIT();

    for (int kt = 0; kt < GNK; kt++) {
        if (kt + 1 < GNK) { load_tile(kt + 1, (kt + 1) & 1); CP_COMMIT(); CP_WAIT(1); }
        else CP_WAIT(0);
        __syncthreads();

        const uint32_t st = sbase + (kt & 1) * STG_B;
#pragma unroll
        for (int ks = 0; ks < 4; ks++) {
            uint32_t bf[4][2];
#pragma unroll
            for (int nf2 = 0; nf2 < 2; nf2++)
                LDSM4(bf[nf2 * 2][0], bf[nf2 * 2][1], bf[nf2 * 2 + 1][0], bf[nf2 * 2 + 1][1],
                      st + BB_OFF + SW128((b_row + nf2 * 16) * 128 + ks * 32 + b_sec));
#pragma unroll
            for (int mf = 0; mf < 4; mf++) {
                uint32_t ah[4];
                LDSM4(ah[0], ah[1], ah[2], ah[3],
                      st + AH_OFF + SW128((a_row + mf * 16) * 128 + ks * 32 + a_sec));
#pragma unroll
                for (int nf = 0; nf < 4; nf++)
                    MMA16816(acc[mf][nf], ah, bf[nf]);
            }
        }
        __syncthreads();
    }

    // Epilogue
#pragma unroll
    for (int nf = 0; nf < 4; nf++) {
        const int col = n0 + wn * 32 + nf * 8 + (lane & 3) * 2;
        const float b0 = __ldg(bias + col), b1 = __ldg(bias + col + 1);
        float cm0 = -3.402823466e38f, cm1 = -3.402823466e38f;
#pragma unroll
        for (int mf = 0; mf < 4; mf++) {
            const int row = m0 + mf * 16 + (lane >> 2);
            float v0 = acc[mf][nf][0] + b0, v1 = acc[mf][nf][1] + b1;
            float v2 = acc[mf][nf][2] + b0, v3 = acc[mf][nf][3] + b1;
            if (!split) {
                float* c0 = Cf + blockIdx.z * sC + (long)row * N + col;
                float2 p0; p0.x = v0; p0.y = v1; *(float2*)c0 = p0;
                float2 p1; p1.x = v2; p1.y = v3; *(float2*)(c0 + 8 * N) = p1;
            } else {
                __half2 p;
                p.x = __float2half_rn(v0); p.y = __float2half_rn(v1);
                *(__half2*)(Cs + (long)row * DIM + col) = p;
                p.x = __float2half_rn(v2); p.y = __float2half_rn(v3);
                *(__half2*)(Cs + (long)(row + 8) * DIM + col) = p;
            }
            cm0 = fmaxf(cm0, fmaxf(v0, v2));
            cm1 = fmaxf(cm1, fmaxf(v1, v3));
        }
        if (col < kmaxN) {       // uniform across warp (kmaxN multiple of 32)
#pragma unroll
            for (int sh = 4; sh < 32; sh <<= 1) {
                cm0 = fmaxf(cm0, __shfl_xor_sync(0xffffffffu, cm0, sh));
                cm1 = fmaxf(cm1, __shfl_xor_sync(0xffffffffu, cm1, sh));
            }
            if ((lane >> 2) == 0) {
                const int b_idx = m0 >> 12;     // 4096 rows per batch
                atomicMax(kmaxKey + b_idx * DIM + col, fkey(cm0));
                atomicMax(kmaxKey + b_idx * DIM + col + 1, fkey(cm1));
            }
        }
    }
}

// ---------------------------------------------------------------------------
// init: zero softmax accumulators (persisted device globals)
// ---------------------------------------------------------------------------
__global__ __launch_bounds__(256)
void init_stats()
{
    int i = blockIdx.x * 256 + threadIdx.x;
    if (i < BATCH * DIM) { g_kmaxKey[i] = 0u; g_Z[i] = 0.f; }
}

// ---------------------------------------------------------------------------
// fp16 conversions
// ---------------------------------------------------------------------------
// Activations: [M,1024] f32 -> [M,1024] fp16
__global__ __launch_bounds__(256)
void split_act(const float* __restrict__ in, __half* __restrict__ out, long total4)
{
    for (long idx = blockIdx.x * 256L + threadIdx.x; idx < total4; idx += gridDim.x * 256L) {
        float4 v = ((const float4*)in)[idx];
        __half2 p0, p1;
        p0.x = __float2half_rn(v.x); p0.y = __float2half_rn(v.y);
        p1.x = __float2half_rn(v.z); p1.y = __float2half_rn(v.w);
        ((__half2*)out)[idx * 2] = p0;
        ((__half2*)out)[idx * 2 + 1] = p1;
    }
}

// Weights (transpose): in [1024,N] f32 -> out [N,1024] fp16
__global__ __launch_bounds__(256)
void split_wt(const float* __restrict__ in, __half* __restrict__ out,
              int N, long sin, long sout)
{
    __shared__ float t[32][33];
    in += blockIdx.z * sin; out += blockIdx.z * sout;
    const int n0 = blockIdx.x * 32, k0 = blockIdx.y * 32;
    const int tx = threadIdx.x & 31, ty = threadIdx.x >> 5;
#pragma unroll
    for (int i = 0; i < 4; i++)
        t[ty + i * 8][tx] = in[(long)(k0 + ty + i * 8) * N + n0 + tx];
    __syncthreads();
#pragma unroll
    for (int i = 0; i < 4; i++) {
        const int nn = ty + i * 8;
        out[(long)(n0 + nn) * DIM + k0 + tx] = __float2half_rn(t[tx][nn]);
    }
}

// ---------------------------------------------------------------------------
// Context partial with fused exp + Z accumulation.
// grid (64, TSPL): each block: one (b,h) over a 256-timestep slice.
// ---------------------------------------------------------------------------
__global__ __launch_bounds__(256)
void context_part()
{
    const int bh = blockIdx.x;
    const int tc = blockIdx.y;
    const int b = bh >> 4;
    const int h = bh & 15;

    const float* kbase = g_kv + (long)b * TLEN * (2 * DIM) + h * HD;
    const float* vbase = kbase + DIM;

    __shared__ float ks[32][68];
    __shared__ float vs[32][68];
    __shared__ float kmaxs[64];
    __shared__ float sZ[64];

    const int tid = threadIdx.x;
    const int tx = tid & 15;
    const int ty = tid >> 4;

    if (tid < 64) {
        kmaxs[tid] = fdec(g_kmaxKey[b * DIM + h * HD + tid]);
        sZ[tid] = 0.f;
    }
    __syncthreads();

    const int c4 = (tid & 15) * 4;
    float4 km;
    km.x = kmaxs[c4]; km.y = kmaxs[c4 + 1]; km.z = kmaxs[c4 + 2]; km.w = kmaxs[c4 + 3];
    float z0 = 0.f, z1 = 0.f, z2 = 0.f, z3 = 0.f;

    float acc[4][4];
#pragma unroll
    for (int i = 0; i < 4; i++)
#pragma unroll
        for (int j = 0; j < 4; j++) acc[i][j] = 0.f;

    const int tspan = TLEN / TSPL;    // 256
    for (int t0 = tc * tspan; t0 < tc * tspan + tspan; t0 += 32) {
#pragma unroll
        for (int ii = 0; ii < 2; ii++) {
            const int i = tid + ii * 256;
            const int r = i >> 4;
            float4 kv4 = *(const float4*)(kbase + (long)(t0 + r) * (2 * DIM) + c4);
            float4 e;
            e.x = expf(kv4.x - km.x); e.y = expf(kv4.y - km.y);
            e.z = expf(kv4.z - km.z); e.w = expf(kv4.w - km.w);
            *(float4*)&ks[r][c4] = e;
            z0 += e.x; z1 += e.y; z2 += e.z; z3 += e.w;
            *(float4*)&vs[r][c4] = *(const float4*)(vbase + (long)(t0 + r) * (2 * DIM) + c4);
        }
        __syncthreads();
#pragma unroll 8
        for (int kk = 0; kk < 32; kk++) {
            float rd[4], rv[4];
#pragma unroll
            for (int i = 0; i < 4; i++) rd[i] = ks[kk][ty * 4 + i];
#pragma unroll
            for (int j = 0; j < 4; j++) rv[j] = vs[kk][tx * 4 + j];
#pragma unroll
            for (int i = 0; i < 4; i++)
#pragma unroll
                for (int j = 0; j < 4; j++)
                    acc[i][j] = fmaf(rd[i], rv[j], acc[i][j]);
        }
        __syncthreads();
    }

    atomicAdd(&sZ[c4], z0);
    atomicAdd(&sZ[c4 + 1], z1);
    atomicAdd(&sZ[c4 + 2], z2);
    atomicAdd(&sZ[c4 + 3], z3);

    float* out = g_Cp + ((long)bh * TSPL + tc) * (HD * HD);
#pragma unroll
    for (int i = 0; i < 4; i++)
#pragma unroll
        for (int j = 0; j < 4; j++)
            out[(ty * 4 + i) * HD + tx * 4 + j] = acc[i][j];

    __syncthreads();
    if (tid < 64)
        atomicAdd(&g_Z[b * DIM + h * HD + tid], sZ[tid]);
}

__global__ __launch_bounds__(256)
void context_reduce()
{
    const int bh = blockIdx.x;
    const int b = bh >> 4, h = bh & 15;
    for (int i = threadIdx.x; i < HD * HD; i += 256) {
        float s = 0.f;
#pragma unroll
        for (int c = 0; c < TSPL; c++)
            s += g_Cp[((long)bh * TSPL + c) * (HD * HD) + i];
        const int d = i >> 6;
        g_Cn[(long)bh * (HD * HD) + i] = s / g_Z[b * DIM + h * HD + d];
    }
}

// ---------------------------------------------------------------------------
// Expand: E_b[h*64+d][n] = sum_w Cn[b,h][d][w] * W_out[h*64+w][n]
// ---------------------------------------------------------------------------
__global__ __launch_bounds__(256)
void expand_kernel(const float* __restrict__ w_out)
{
    const int bh = blockIdx.y;
    const int b = bh >> 4;
    const int h = bh & 15;
    const int cb = blockIdx.x * 128;

    __shared__ float cs[64][64];
    __shared__ float ws[64][128];

    const int tid = threadIdx.x;
    for (int i = tid; i < 1024; i += 256) {
        const int r = i >> 4;
        const int c = (i & 15) * 4;
        *(float4*)&cs[r][c] = *(const float4*)(g_Cn + (long)bh * 4096 + r * 64 + c);
    }
    for (int i = tid; i < 2048; i += 256) {
        const int r = i >> 5;
        const int c = (i & 31) * 4;
        *(float4*)&ws[r][c] = *(const float4*)(w_out + (long)(h * HD + r) * DIM + cb + c);
    }
    __syncthreads();

    const int tx = tid & 31;
    const int ty = tid >> 5;

    float acc[8][4];
#pragma unroll
    for (int rr = 0; rr < 8; rr++)
#pragma unroll
        for (int j = 0; j < 4; j++) acc[rr][j] = 0.f;

#pragma unroll 4
    for (int w = 0; w < 64; w++) {
        float4 wv = *(float4*)&ws[w][tx * 4];
#pragma unroll
        for (int rr = 0; rr < 8; rr++) {
            const float cv = cs[ty + rr * 8][w];
            acc[rr][0] = fmaf(cv, wv.x, acc[rr][0]);
            acc[rr][1] = fmaf(cv, wv.y, acc[rr][1]);
            acc[rr][2] = fmaf(cv, wv.z, acc[rr][2]);
            acc[rr][3] = fmaf(cv, wv.w, acc[rr][3]);
        }
    }

#pragma unroll
    for (int rr = 0; rr < 8; rr++) {
        const int row = ty + rr * 8;
        float4 o; o.x = acc[rr][0]; o.y = acc[rr][1]; o.z = acc[rr][2]; o.w = acc[rr][3];
        *(float4*)(g_E + ((long)b * DIM + h * HD + row) * DIM + cb + tx * 4) = o;
    }
}

// ---------------------------------------------------------------------------
extern "C" void kernel_launch(void* const* d_in, const int* in_sizes, int n_in,
                              void* d_out, int out_size)
{
    const float* x     = (const float*)d_in[0];
    const float* z     = (const float*)d_in[1];
    const float* w_q   = (const float*)d_in[2];
    const float* b_q   = (const float*)d_in[3];
    const float* w_kv  = (const float*)d_in[4];
    const float* b_kv  = (const float*)d_in[5];
    const float* w_out = (const float*)d_in[6];
    const float* b_out = (const float*)d_in[7];
    float* out = (float*)d_out;

    float *kv, *E;
    unsigned* kmaxKey;
    __half *zs, *xs, *qs, *wkvs, *wqs, *Es;
    cudaGetSymbolAddress((void**)&kv, g_kv);
    cudaGetSymbolAddress((void**)&E, g_E);
    cudaGetSymbolAddress((void**)&kmaxKey, g_kmaxKey);
    cudaGetSymbolAddress((void**)&zs, g_zs);
    cudaGetSymbolAddress((void**)&xs, g_xs);
    cudaGetSymbolAddress((void**)&qs, g_qs);
    cudaGetSymbolAddress((void**)&wkvs, g_wkvs);
    cudaGetSymbolAddress((void**)&wqs, g_wqs);
    cudaGetSymbolAddress((void**)&Es, g_Es);

    cudaFuncSetAttribute(gemm_mma, cudaFuncAttributeMaxDynamicSharedMemorySize, GSMEM);

    const int M = BATCH * TLEN;          // 16384
    const long tot4 = (long)M * DIM / 4;

    // 0. zero softmax accumulators (device globals persist across replays)
    init_stats<<<16, 256>>>();
    // 1. weight transposes (fp16)
    { dim3 g(2 * DIM / 32, DIM / 32, 1); split_wt<<<g, 256>>>(w_kv, wkvs, 2 * DIM, 0, 0); }
    { dim3 g(DIM / 32, DIM / 32, 1);     split_wt<<<g, 256>>>(w_q, wqs, DIM, 0, 0); }
    // 2. activation conversions (fp16)
    split_act<<<2048, 256>>>(z, zs, tot4);
    split_act<<<2048, 256>>>(x, xs, tot4);
    // 3. kv = z @ w_kv + b_kv  (fp32 out; fused per-(b,col) max of k half)
    { dim3 g(2 * DIM / 256, M / 64, 1);
      gemm_mma<<<g, 256, GSMEM>>>(zs, wkvs, b_kv, kv, nullptr, 2 * DIM, 0,
                                  kmaxKey, DIM, 0, 0, 0); }
    // 4. q = x @ w_q + b_q  (fp16 out straight into g_qs)
    { dim3 g(DIM / 256, M / 64, 1);
      gemm_mma<<<g, 256, GSMEM>>>(xs, wqs, b_q, nullptr, qs, DIM, 1,
                                  kmaxKey, 0, 0, 0, 0); }
    // 5. context (fused exp + Z; partials over T, then reduce+normalize)
    { dim3 g(BATCH * NH, TSPL); context_part<<<g, 256>>>(); }
    context_reduce<<<BATCH * NH, 256>>>();
    // 6. E_b = blockdiag(Cn) @ W_out
    { dim3 g(DIM / 128, BATCH * NH); expand_kernel<<<g, 256>>>(w_out); }
    // 7. E transpose (batched, fp16)
    { dim3 g(DIM / 32, DIM / 32, BATCH); split_wt<<<g, 256>>>(E, Es, DIM, (long)DIM * DIM, (long)DIM * DIM); }
    // 8. out_b = q_b @ E_b + b_out (batched, fp32 out)
    { dim3 g(DIM / 256, TLEN / 64, BATCH);
      gemm_mma<<<g, 256, GSMEM>>>(qs, Es, b_out, out, nullptr, DIM, 0,
                                  kmaxKey, 0, (long)TLEN * DIM, (long)DIM * DIM, (long)TLEN * DIM); }
}